// round 7
// baseline (speedup 1.0000x reference)
#include <cuda_runtime.h>
#include <math.h>

#define B_   4
#define H_   8
#define S_   2048
#define D_   16
#define TILE 128
#define QPB  128          // threads per CTA
#define QPT  2            // queries per thread
#define QTILE (QPB*QPT)   // 256 queries per CTA

// ---- packed f32x2 helpers (sm_100+ PTX; FFMA2 in SASS) ----
__device__ __forceinline__ unsigned long long ffma2(unsigned long long a,
                                                    unsigned long long b,
                                                    unsigned long long c) {
    unsigned long long d;
    asm("fma.rn.f32x2 %0, %1, %2, %3;" : "=l"(d) : "l"(a), "l"(b), "l"(c));
    return d;
}
__device__ __forceinline__ unsigned long long fadd2(unsigned long long a,
                                                    unsigned long long b) {
    unsigned long long d;
    asm("add.rn.f32x2 %0, %1, %2;" : "=l"(d) : "l"(a), "l"(b));
    return d;
}
__device__ __forceinline__ float ex2f(float x) {
    float y; asm("ex2.approx.ftz.f32 %0, %1;" : "=f"(y) : "f"(x)); return y;
}
__device__ __forceinline__ float rcpf(float x) {
    float y; asm("rcp.approx.ftz.f32 %0, %1;" : "=f"(y) : "f"(x)); return y;
}

// p = exp(10*tanh(x)); s = 2x*log2e comes out of the prescaled dot product:
// e = 2^s = exp(2x); r = 1/(e+1); p = 2^(fma(r, -20*log2e, 10*log2e))
#define C_A  (-28.853900817779268f)  // -20*log2(e)
#define C_B  ( 14.426950408889634f)  //  10*log2(e)

struct KRow { ulonglong2 r0, r1, r2, r3; };   // 16 floats packed as f32x2

__device__ __forceinline__ float dot16(const unsigned long long* qp, const KRow& k) {
    unsigned long long d0, d1;
    d0 = ffma2(qp[0], k.r0.x, 0ull);
    d1 = ffma2(qp[1], k.r0.y, 0ull);
    d0 = ffma2(qp[2], k.r1.x, d0);
    d1 = ffma2(qp[3], k.r1.y, d1);
    d0 = ffma2(qp[4], k.r2.x, d0);
    d1 = ffma2(qp[5], k.r2.y, d1);
    d0 = ffma2(qp[6], k.r3.x, d0);
    d1 = ffma2(qp[7], k.r3.y, d1);
    unsigned long long ds = fadd2(d0, d1);
    float lo, hi;
    asm("mov.b64 {%0, %1}, %2;" : "=f"(lo), "=f"(hi) : "l"(ds));
    return lo + hi;
}
__device__ __forceinline__ float pfun(float s) {
    const float e = ex2f(s);
    const float r = rcpf(e + 1.f);
    return ex2f(fmaf(r, C_A, C_B));
}
__device__ __forceinline__ void pv_acc(unsigned long long* acc, float p, const KRow& v) {
    unsigned long long pp;
    asm("mov.b64 %0, {%1, %1};" : "=l"(pp) : "f"(p));
    acc[0] = ffma2(pp, v.r0.x, acc[0]);
    acc[1] = ffma2(pp, v.r0.y, acc[1]);
    acc[2] = ffma2(pp, v.r1.x, acc[2]);
    acc[3] = ffma2(pp, v.r1.y, acc[3]);
    acc[4] = ffma2(pp, v.r2.x, acc[4]);
    acc[5] = ffma2(pp, v.r2.y, acc[5]);
    acc[6] = ffma2(pp, v.r3.x, acc[6]);
    acc[7] = ffma2(pp, v.r3.y, acc[7]);
}

__global__ __launch_bounds__(QPB, 4)
void attn_kernel(const float* __restrict__ Q, const float* __restrict__ K,
                 const float* __restrict__ V, const int* __restrict__ mask,
                 float* __restrict__ O, float q_prescale /* SCALE*2*log2(e) */) {
    __shared__ float Ks[TILE * D_];
    __shared__ float Vs[TILE * D_];
    __shared__ int   s_wcnt[4];

    const int bh   = blockIdx.y;
    const int b    = bh / H_;
    const int tid  = threadIdx.x;
    const int wid  = tid >> 5;
    const int lane = tid & 31;
    const int q0   = blockIdx.x * QTILE + tid;      // second query: q0 + QPB
    const long long base = (long long)bh * S_ * D_;

    // Load + prescale both query rows, packed f32x2
    unsigned long long qp0[8], qp1[8];
    {
        const float4* qg0 = (const float4*)(Q + base + (long long)q0 * D_);
        const float4* qg1 = (const float4*)(Q + base + (long long)(q0 + QPB) * D_);
        #pragma unroll
        for (int i = 0; i < 4; i++) {
            float4 u = qg0[i], v = qg1[i];
            float a0 = u.x*q_prescale, a1 = u.y*q_prescale;
            float a2 = u.z*q_prescale, a3 = u.w*q_prescale;
            float c0 = v.x*q_prescale, c1 = v.y*q_prescale;
            float c2 = v.z*q_prescale, c3 = v.w*q_prescale;
            asm("mov.b64 %0, {%1, %2};" : "=l"(qp0[2*i+0]) : "f"(a0), "f"(a1));
            asm("mov.b64 %0, {%1, %2};" : "=l"(qp0[2*i+1]) : "f"(a2), "f"(a3));
            asm("mov.b64 %0, {%1, %2};" : "=l"(qp1[2*i+0]) : "f"(c0), "f"(c1));
            asm("mov.b64 %0, {%1, %2};" : "=l"(qp1[2*i+1]) : "f"(c2), "f"(c3));
        }
    }

    unsigned long long acc0[8], acc1[8];
    #pragma unroll
    for (int i = 0; i < 8; i++) { acc0[i] = 0ull; acc1[i] = 0ull; }
    float lsum0 = 0.f, lsum1 = 0.f;

    // mask is 4-byte (bool upcast to int32 or float32); bitwise !=0 handles both
    const int* mrow = mask + (long long)b * S_;

    for (int t0 = 0; t0 < S_; t0 += TILE) {
        // ---- deterministic ballot compaction (no atomics) ----
        const int j    = t0 + tid;
        const int keep = (mrow[j] == 0);
        const unsigned bal = __ballot_sync(0xFFFFFFFFu, keep);
        if (lane == 0) s_wcnt[wid] = __popc(bal);
        __syncthreads();   // publish counts; guards prev-tile readers vs new writes
        int wbase = 0, total = 0;
        #pragma unroll
        for (int w = 0; w < 4; w++) {
            int cw = s_wcnt[w];
            if (w < wid) wbase += cw;
            total += cw;
        }
        if (keep) {
            const int pos = wbase + __popc(bal & ((1u << lane) - 1u));
            const float4* kg = (const float4*)(K + base + (long long)j * D_);
            const float4* vg = (const float4*)(V + base + (long long)j * D_);
            float4* kd = (float4*)(Ks + pos * D_);
            float4* vd = (float4*)(Vs + pos * D_);
            #pragma unroll
            for (int i = 0; i < 4; i++) { kd[i] = kg[i]; vd[i] = vg[i]; }
        }
        __syncthreads();
        const int cnt = total;

        const KRow* ksr = (const KRow*)Ks;
        const KRow* vsr = (const KRow*)Vs;

        int jj = 0;
        for (; jj + 2 <= cnt; jj += 2) {
            // 4 independent dot chains (kA/kB die before V loads -> lower reg peak)
            float sA0, sA1, sB0, sB1;
            {
                KRow kA = ksr[jj], kB = ksr[jj+1];
                sA0 = dot16(qp0, kA);
                sA1 = dot16(qp1, kA);
                sB0 = dot16(qp0, kB);
                sB1 = dot16(qp1, kB);
            }
            // 4 independent MUFU chains
            float pA0 = pfun(sA0);
            float pA1 = pfun(sA1);
            float pB0 = pfun(sB0);
            float pB1 = pfun(sB1);
            lsum0 += pA0; lsum1 += pA1;
            lsum0 += pB0; lsum1 += pB1;
            {
                KRow vA = vsr[jj], vB = vsr[jj+1];
                pv_acc(acc0, pA0, vA);
                pv_acc(acc1, pA1, vA);
                pv_acc(acc0, pB0, vB);
                pv_acc(acc1, pB1, vB);
            }
        }
        if (jj < cnt) {
            KRow kA = ksr[jj];
            float sA0 = dot16(qp0, kA);
            float sA1 = dot16(qp1, kA);
            float pA0 = pfun(sA0);
            float pA1 = pfun(sA1);
            lsum0 += pA0; lsum1 += pA1;
            KRow vA = vsr[jj];
            pv_acc(acc0, pA0, vA);
            pv_acc(acc1, pA1, vA);
        }
        __syncthreads();
    }

    // Epilogue: normalize and store both query rows
    const float inv0 = 1.0f / lsum0;
    const float inv1 = 1.0f / lsum1;
    float4* og0 = (float4*)(O + base + (long long)q0 * D_);
    float4* og1 = (float4*)(O + base + (long long)(q0 + QPB) * D_);
    #pragma unroll
    for (int i = 0; i < 4; i++) {
        float x0, x1, y0, y1;
        asm("mov.b64 {%0, %1}, %2;" : "=f"(x0), "=f"(x1) : "l"(acc0[2*i]));
        asm("mov.b64 {%0, %1}, %2;" : "=f"(y0), "=f"(y1) : "l"(acc0[2*i+1]));
        float4 o; o.x = x0*inv0; o.y = x1*inv0; o.z = y0*inv0; o.w = y1*inv0;
        og0[i] = o;
        asm("mov.b64 {%0, %1}, %2;" : "=f"(x0), "=f"(x1) : "l"(acc1[2*i]));
        asm("mov.b64 {%0, %1}, %2;" : "=f"(y0), "=f"(y1) : "l"(acc1[2*i+1]));
        float4 p; p.x = x0*inv1; p.y = x1*inv1; p.z = y0*inv1; p.w = y1*inv1;
        og1[i] = p;
    }
}

extern "C" void kernel_launch(void* const* d_in, const int* in_sizes, int n_in,
                              void* d_out, int out_size) {
    const float* Q = (const float*)d_in[0];
    const float* K = (const float*)d_in[1];
    const float* V = (const float*)d_in[2];
    const int*   mask = (const int*)d_in[3];
    float* O = (float*)d_out;

    // SCALE = log(400)/log(50)/sqrt(16); fold in 2*log2(e) for the tanh exp
    const float q_prescale =
        (float)((log(400.0) / log(50.0) / 4.0) * 2.0 * 1.4426950408889634);

    dim3 grid(S_ / QTILE, B_ * H_);
    attn_kernel<<<grid, QPB>>>(Q, K, V, mask, O, q_prescale);
}

// round 9
// speedup vs baseline: 1.0943x; 1.0943x over previous
#include <cuda_runtime.h>
#include <math.h>

#define B_   4
#define H_   8
#define S_   2048
#define D_   16
#define TILE 128
#define QPB  128          // threads per CTA
#define QPT  2            // queries per thread
#define QTILE (QPB*QPT)   // 256 queries per CTA
#define KSPLIT 2
#define SKEYS (S_/KSPLIT) // keys per split

// ---- packed f32x2 helpers (sm_100+ PTX; FFMA2 in SASS) ----
__device__ __forceinline__ unsigned long long ffma2(unsigned long long a,
                                                    unsigned long long b,
                                                    unsigned long long c) {
    unsigned long long d;
    asm("fma.rn.f32x2 %0, %1, %2, %3;" : "=l"(d) : "l"(a), "l"(b), "l"(c));
    return d;
}
__device__ __forceinline__ unsigned long long fadd2(unsigned long long a,
                                                    unsigned long long b) {
    unsigned long long d;
    asm("add.rn.f32x2 %0, %1, %2;" : "=l"(d) : "l"(a), "l"(b));
    return d;
}
__device__ __forceinline__ float ex2f(float x) {
    float y; asm("ex2.approx.ftz.f32 %0, %1;" : "=f"(y) : "f"(x)); return y;
}
__device__ __forceinline__ float rcpf(float x) {
    float y; asm("rcp.approx.ftz.f32 %0, %1;" : "=f"(y) : "f"(x)); return y;
}

// p = exp(10*tanh(x)); s = 2x*log2e comes out of the prescaled dot product
#define C_A  (-28.853900817779268f)  // -20*log2(e)
#define C_B  ( 14.426950408889634f)  //  10*log2(e)

struct KRow { ulonglong2 r0, r1, r2, r3; };   // 16 floats packed as f32x2

__device__ __forceinline__ float dot16(const unsigned long long* qp, const KRow& k) {
    unsigned long long d0, d1;
    d0 = ffma2(qp[0], k.r0.x, 0ull);
    d1 = ffma2(qp[1], k.r0.y, 0ull);
    d0 = ffma2(qp[2], k.r1.x, d0);
    d1 = ffma2(qp[3], k.r1.y, d1);
    d0 = ffma2(qp[4], k.r2.x, d0);
    d1 = ffma2(qp[5], k.r2.y, d1);
    d0 = ffma2(qp[6], k.r3.x, d0);
    d1 = ffma2(qp[7], k.r3.y, d1);
    unsigned long long ds = fadd2(d0, d1);
    float lo, hi;
    asm("mov.b64 {%0, %1}, %2;" : "=f"(lo), "=f"(hi) : "l"(ds));
    return lo + hi;
}
__device__ __forceinline__ float pfun(float s) {
    const float e = ex2f(s);
    const float r = rcpf(e + 1.f);
    return ex2f(fmaf(r, C_A, C_B));
}
__device__ __forceinline__ void pv_acc(unsigned long long* acc, float p, const KRow& v) {
    unsigned long long pp;
    asm("mov.b64 %0, {%1, %1};" : "=l"(pp) : "f"(p));
    acc[0] = ffma2(pp, v.r0.x, acc[0]);
    acc[1] = ffma2(pp, v.r0.y, acc[1]);
    acc[2] = ffma2(pp, v.r1.x, acc[2]);
    acc[3] = ffma2(pp, v.r1.y, acc[3]);
    acc[4] = ffma2(pp, v.r2.x, acc[4]);
    acc[5] = ffma2(pp, v.r2.y, acc[5]);
    acc[6] = ffma2(pp, v.r3.x, acc[6]);
    acc[7] = ffma2(pp, v.r3.y, acc[7]);
}

// Split-K scratch (allocation-free: __device__ globals)
__device__ float g_pacc [KSPLIT][B_*H_*S_*D_];   // unnormalized P·V partials
__device__ float g_plsum[KSPLIT][B_*H_*S_];      // softmax denominators

__global__ __launch_bounds__(QPB, 4)
void attn_kernel(const float* __restrict__ Q, const float* __restrict__ K,
                 const float* __restrict__ V, const int* __restrict__ mask,
                 float q_prescale /* SCALE*2*log2(e) */) {
    __shared__ float Ks[TILE * D_];
    __shared__ float Vs[TILE * D_];
    __shared__ int   s_wcnt[4];

    const int bh   = blockIdx.y;
    const int b    = bh / H_;
    const int kz   = blockIdx.z;                    // key split
    const int tid  = threadIdx.x;
    const int wid  = tid >> 5;
    const int lane = tid & 31;
    const int q0   = blockIdx.x * QTILE + tid;      // second query: q0 + QPB
    const long long base = (long long)bh * S_ * D_;

    // Load + prescale both query rows, packed f32x2
    unsigned long long qp0[8], qp1[8];
    {
        const float4* qg0 = (const float4*)(Q + base + (long long)q0 * D_);
        const float4* qg1 = (const float4*)(Q + base + (long long)(q0 + QPB) * D_);
        #pragma unroll
        for (int i = 0; i < 4; i++) {
            float4 u = qg0[i], v = qg1[i];
            float a0 = u.x*q_prescale, a1 = u.y*q_prescale;
            float a2 = u.z*q_prescale, a3 = u.w*q_prescale;
            float c0 = v.x*q_prescale, c1 = v.y*q_prescale;
            float c2 = v.z*q_prescale, c3 = v.w*q_prescale;
            asm("mov.b64 %0, {%1, %2};" : "=l"(qp0[2*i+0]) : "f"(a0), "f"(a1));
            asm("mov.b64 %0, {%1, %2};" : "=l"(qp0[2*i+1]) : "f"(a2), "f"(a3));
            asm("mov.b64 %0, {%1, %2};" : "=l"(qp1[2*i+0]) : "f"(c0), "f"(c1));
            asm("mov.b64 %0, {%1, %2};" : "=l"(qp1[2*i+1]) : "f"(c2), "f"(c3));
        }
    }

    unsigned long long acc0[8], acc1[8];
    #pragma unroll
    for (int i = 0; i < 8; i++) { acc0[i] = 0ull; acc1[i] = 0ull; }
    float lsum0 = 0.f, lsum1 = 0.f;

    // mask is 4-byte (bool upcast); bitwise !=0 handles int32 or float32
    const int* mrow = mask + (long long)b * S_;

    const int kbeg = kz * SKEYS, kend = kbeg + SKEYS;
    for (int t0 = kbeg; t0 < kend; t0 += TILE) {
        // ---- deterministic ballot compaction (no atomics) ----
        const int j    = t0 + tid;
        const int keep = (mrow[j] == 0);
        const unsigned bal = __ballot_sync(0xFFFFFFFFu, keep);
        if (lane == 0) s_wcnt[wid] = __popc(bal);
        __syncthreads();   // publish counts; guards prev-tile readers vs new writes
        int wbase = 0, total = 0;
        #pragma unroll
        for (int w = 0; w < 4; w++) {
            int cw = s_wcnt[w];
            if (w < wid) wbase += cw;
            total += cw;
        }
        if (keep) {
            const int pos = wbase + __popc(bal & ((1u << lane) - 1u));
            const float4* kg = (const float4*)(K + base + (long long)j * D_);
            const float4* vg = (const float4*)(V + base + (long long)j * D_);
            float4* kd = (float4*)(Ks + pos * D_);
            float4* vd = (float4*)(Vs + pos * D_);
            #pragma unroll
            for (int i = 0; i < 4; i++) { kd[i] = kg[i]; vd[i] = vg[i]; }
        }
        __syncthreads();
        const int cnt = total;

        const KRow* ksr = (const KRow*)Ks;
        const KRow* vsr = (const KRow*)Vs;

        for (int jj = 0; jj < cnt; ++jj) {
            float s0, s1;
            {
                KRow kA = ksr[jj];
                s0 = dot16(qp0, kA);
                s1 = dot16(qp1, kA);
            }
            float p0 = pfun(s0);
            float p1 = pfun(s1);
            lsum0 += p0; lsum1 += p1;
            {
                KRow vA = vsr[jj];
                pv_acc(acc0, p0, vA);
                pv_acc(acc1, p1, vA);
            }
        }
        __syncthreads();
    }

    // Epilogue: write unnormalized partials to split-K scratch
    const long long qidx0 = (long long)bh * S_ + q0;
    const long long qidx1 = qidx0 + QPB;
    g_plsum[kz][qidx0] = lsum0;
    g_plsum[kz][qidx1] = lsum1;
    float4* pa0 = (float4*)(&g_pacc[kz][qidx0 * D_]);
    float4* pa1 = (float4*)(&g_pacc[kz][qidx1 * D_]);
    #pragma unroll
    for (int i = 0; i < 4; i++) {
        float x0, x1, y0, y1;
        asm("mov.b64 {%0, %1}, %2;" : "=f"(x0), "=f"(x1) : "l"(acc0[2*i]));
        asm("mov.b64 {%0, %1}, %2;" : "=f"(y0), "=f"(y1) : "l"(acc0[2*i+1]));
        float4 o; o.x = x0; o.y = x1; o.z = y0; o.w = y1;
        pa0[i] = o;
        asm("mov.b64 {%0, %1}, %2;" : "=f"(x0), "=f"(x1) : "l"(acc1[2*i]));
        asm("mov.b64 {%0, %1}, %2;" : "=f"(y0), "=f"(y1) : "l"(acc1[2*i+1]));
        float4 p; p.x = x0; p.y = x1; p.z = y0; p.w = y1;
        pa1[i] = p;
    }
}

// Combine: O = (acc0+acc1) / (lsum0+lsum1). 1 float4 per thread.
__global__ __launch_bounds__(256)
void reduce_kernel(float* __restrict__ O) {
    const int i4 = blockIdx.x * 256 + threadIdx.x;          // 0 .. 262143
    const int qi = i4 >> 2;                                 // query row (D=16 -> 4 float4/row)
    const float l = g_plsum[0][qi] + g_plsum[1][qi];
    const float inv = 1.0f / l;
    const float4 a = ((const float4*)g_pacc[0])[i4];
    const float4 c = ((const float4*)g_pacc[1])[i4];
    float4 o;
    o.x = (a.x + c.x) * inv;
    o.y = (a.y + c.y) * inv;
    o.z = (a.z + c.z) * inv;
    o.w = (a.w + c.w) * inv;
    ((float4*)O)[i4] = o;
}

extern "C" void kernel_launch(void* const* d_in, const int* in_sizes, int n_in,
                              void* d_out, int out_size) {
    const float* Q = (const float*)d_in[0];
    const float* K = (const float*)d_in[1];
    const float* V = (const float*)d_in[2];
    const int*   mask = (const int*)d_in[3];
    float* O = (float*)d_out;

    // SCALE = log(400)/log(50)/sqrt(16); fold in 2*log2(e) for the tanh exp
    const float q_prescale =
        (float)((log(400.0) / log(50.0) / 4.0) * 2.0 * 1.4426950408889634);

    dim3 grid(S_ / QTILE, B_ * H_, KSPLIT);
    attn_kernel<<<grid, QPB>>>(Q, K, V, mask, q_prescale);

    const int total4 = B_ * H_ * S_ * D_ / 4;               // 262144
    reduce_kernel<<<total4 / 256, 256>>>(O);
}

// round 10
// speedup vs baseline: 1.0949x; 1.0005x over previous
#include <cuda_runtime.h>
#include <math.h>

#define B_   4
#define H_   8
#define S_   2048
#define D_   16
#define TILE 128
#define QPB  128          // threads per CTA
#define QPT  2            // queries per thread
#define QTILE (QPB*QPT)   // 256 queries per CTA
#define KSPLIT 2
#define SKEYS (S_/KSPLIT) // keys per split

// ---- packed f32x2 helpers (sm_100+ PTX; FFMA2 in SASS) ----
__device__ __forceinline__ unsigned long long ffma2(unsigned long long a,
                                                    unsigned long long b,
                                                    unsigned long long c) {
    unsigned long long d;
    asm("fma.rn.f32x2 %0, %1, %2, %3;" : "=l"(d) : "l"(a), "l"(b), "l"(c));
    return d;
}
__device__ __forceinline__ unsigned long long fadd2(unsigned long long a,
                                                    unsigned long long b) {
    unsigned long long d;
    asm("add.rn.f32x2 %0, %1, %2;" : "=l"(d) : "l"(a), "l"(b));
    return d;
}
__device__ __forceinline__ float ex2f(float x) {
    float y; asm("ex2.approx.ftz.f32 %0, %1;" : "=f"(y) : "f"(x)); return y;
}
__device__ __forceinline__ float rcpf(float x) {
    float y; asm("rcp.approx.ftz.f32 %0, %1;" : "=f"(y) : "f"(x)); return y;
}

// p = exp(10*tanh(x)); s = 2x*log2e comes out of the prescaled dot product
#define C_A  (-28.853900817779268f)  // -20*log2(e)
#define C_B  ( 14.426950408889634f)  //  10*log2(e)

struct KRow { ulonglong2 r0, r1, r2, r3; };   // 16 floats packed as f32x2

__device__ __forceinline__ float dot16(const unsigned long long* qp, const KRow& k) {
    unsigned long long d0, d1;
    d0 = ffma2(qp[0], k.r0.x, 0ull);
    d1 = ffma2(qp[1], k.r0.y, 0ull);
    d0 = ffma2(qp[2], k.r1.x, d0);
    d1 = ffma2(qp[3], k.r1.y, d1);
    d0 = ffma2(qp[4], k.r2.x, d0);
    d1 = ffma2(qp[5], k.r2.y, d1);
    d0 = ffma2(qp[6], k.r3.x, d0);
    d1 = ffma2(qp[7], k.r3.y, d1);
    unsigned long long ds = fadd2(d0, d1);
    float lo, hi;
    asm("mov.b64 {%0, %1}, %2;" : "=f"(lo), "=f"(hi) : "l"(ds));
    return lo + hi;
}
__device__ __forceinline__ float pfun(float s) {
    const float e = ex2f(s);
    const float r = rcpf(e + 1.f);
    return ex2f(fmaf(r, C_A, C_B));
}
__device__ __forceinline__ void pv_acc(unsigned long long* acc, float p, const KRow& v) {
    unsigned long long pp;
    asm("mov.b64 %0, {%1, %1};" : "=l"(pp) : "f"(p));
    acc[0] = ffma2(pp, v.r0.x, acc[0]);
    acc[1] = ffma2(pp, v.r0.y, acc[1]);
    acc[2] = ffma2(pp, v.r1.x, acc[2]);
    acc[3] = ffma2(pp, v.r1.y, acc[3]);
    acc[4] = ffma2(pp, v.r2.x, acc[4]);
    acc[5] = ffma2(pp, v.r2.y, acc[5]);
    acc[6] = ffma2(pp, v.r3.x, acc[6]);
    acc[7] = ffma2(pp, v.r3.y, acc[7]);
}

// Split-K scratch (allocation-free: __device__ globals)
__device__ float g_pacc [KSPLIT][B_*H_*S_*D_];   // unnormalized P·V partials
__device__ float g_plsum[KSPLIT][B_*H_*S_];      // softmax denominators

__global__ __launch_bounds__(QPB, 3)
void attn_kernel(const float* __restrict__ Q, const float* __restrict__ K,
                 const float* __restrict__ V, const int* __restrict__ mask,
                 float q_prescale /* SCALE*2*log2(e) */) {
    __shared__ float Ks[TILE * D_];
    __shared__ float Vs[TILE * D_];
    __shared__ int   s_wcnt[4];

    const int bh   = blockIdx.y;
    const int b    = bh / H_;
    const int kz   = blockIdx.z;                    // key split
    const int tid  = threadIdx.x;
    const int wid  = tid >> 5;
    const int lane = tid & 31;
    const int q0   = blockIdx.x * QTILE + tid;      // second query: q0 + QPB
    const long long base = (long long)bh * S_ * D_;

    // Load + prescale both query rows, packed f32x2
    unsigned long long qp0[8], qp1[8];
    {
        const float4* qg0 = (const float4*)(Q + base + (long long)q0 * D_);
        const float4* qg1 = (const float4*)(Q + base + (long long)(q0 + QPB) * D_);
        #pragma unroll
        for (int i = 0; i < 4; i++) {
            float4 u = qg0[i], v = qg1[i];
            float a0 = u.x*q_prescale, a1 = u.y*q_prescale;
            float a2 = u.z*q_prescale, a3 = u.w*q_prescale;
            float c0 = v.x*q_prescale, c1 = v.y*q_prescale;
            float c2 = v.z*q_prescale, c3 = v.w*q_prescale;
            asm("mov.b64 %0, {%1, %2};" : "=l"(qp0[2*i+0]) : "f"(a0), "f"(a1));
            asm("mov.b64 %0, {%1, %2};" : "=l"(qp0[2*i+1]) : "f"(a2), "f"(a3));
            asm("mov.b64 %0, {%1, %2};" : "=l"(qp1[2*i+0]) : "f"(c0), "f"(c1));
            asm("mov.b64 %0, {%1, %2};" : "=l"(qp1[2*i+1]) : "f"(c2), "f"(c3));
        }
    }

    unsigned long long acc0[8], acc1[8];
    #pragma unroll
    for (int i = 0; i < 8; i++) { acc0[i] = 0ull; acc1[i] = 0ull; }
    float lsum0 = 0.f, lsum1 = 0.f;

    // mask is 4-byte (bool upcast); bitwise !=0 handles int32 or float32
    const int* mrow = mask + (long long)b * S_;

    const int kbeg = kz * SKEYS, kend = kbeg + SKEYS;
    for (int t0 = kbeg; t0 < kend; t0 += TILE) {
        // ---- deterministic ballot compaction (no atomics) ----
        const int j    = t0 + tid;
        const int keep = (mrow[j] == 0);
        const unsigned bal = __ballot_sync(0xFFFFFFFFu, keep);
        if (lane == 0) s_wcnt[wid] = __popc(bal);
        __syncthreads();   // publish counts; guards prev-tile readers vs new writes
        int wbase = 0, total = 0;
        #pragma unroll
        for (int w = 0; w < 4; w++) {
            int cw = s_wcnt[w];
            if (w < wid) wbase += cw;
            total += cw;
        }
        if (keep) {
            const int pos = wbase + __popc(bal & ((1u << lane) - 1u));
            const float4* kg = (const float4*)(K + base + (long long)j * D_);
            const float4* vg = (const float4*)(V + base + (long long)j * D_);
            float4* kd = (float4*)(Ks + pos * D_);
            float4* vd = (float4*)(Vs + pos * D_);
            #pragma unroll
            for (int i = 0; i < 4; i++) { kd[i] = kg[i]; vd[i] = vg[i]; }
        }
        __syncthreads();
        const int cnt = total;

        const KRow* ksr = (const KRow*)Ks;
        const KRow* vsr = (const KRow*)Vs;

        int jj = 0;
        for (; jj + 2 <= cnt; jj += 2) {
            // 4 independent dot chains; kA/kB die before V loads
            float sA0, sA1, sB0, sB1;
            {
                KRow kA = ksr[jj], kB = ksr[jj+1];
                sA0 = dot16(qp0, kA);
                sA1 = dot16(qp1, kA);
                sB0 = dot16(qp0, kB);
                sB1 = dot16(qp1, kB);
            }
            // 4 independent MUFU chains
            float pA0 = pfun(sA0);
            float pA1 = pfun(sA1);
            float pB0 = pfun(sB0);
            float pB1 = pfun(sB1);
            lsum0 += pA0; lsum1 += pA1;
            lsum0 += pB0; lsum1 += pB1;
            {
                KRow vA = vsr[jj], vB = vsr[jj+1];
                pv_acc(acc0, pA0, vA);
                pv_acc(acc1, pA1, vA);
                pv_acc(acc0, pB0, vB);
                pv_acc(acc1, pB1, vB);
            }
        }
        if (jj < cnt) {
            KRow kA = ksr[jj];
            float sA0 = dot16(qp0, kA);
            float sA1 = dot16(qp1, kA);
            float pA0 = pfun(sA0);
            float pA1 = pfun(sA1);
            lsum0 += pA0; lsum1 += pA1;
            KRow vA = vsr[jj];
            pv_acc(acc0, pA0, vA);
            pv_acc(acc1, pA1, vA);
        }
        __syncthreads();
    }

    // Epilogue: write unnormalized partials to split-K scratch
    const long long qidx0 = (long long)bh * S_ + q0;
    const long long qidx1 = qidx0 + QPB;
    g_plsum[kz][qidx0] = lsum0;
    g_plsum[kz][qidx1] = lsum1;
    float4* pa0 = (float4*)(&g_pacc[kz][qidx0 * D_]);
    float4* pa1 = (float4*)(&g_pacc[kz][qidx1 * D_]);
    #pragma unroll
    for (int i = 0; i < 4; i++) {
        float x0, x1, y0, y1;
        asm("mov.b64 {%0, %1}, %2;" : "=f"(x0), "=f"(x1) : "l"(acc0[2*i]));
        asm("mov.b64 {%0, %1}, %2;" : "=f"(y0), "=f"(y1) : "l"(acc0[2*i+1]));
        float4 o; o.x = x0; o.y = x1; o.z = y0; o.w = y1;
        pa0[i] = o;
        asm("mov.b64 {%0, %1}, %2;" : "=f"(x0), "=f"(x1) : "l"(acc1[2*i]));
        asm("mov.b64 {%0, %1}, %2;" : "=f"(y0), "=f"(y1) : "l"(acc1[2*i+1]));
        float4 p; p.x = x0; p.y = x1; p.z = y0; p.w = y1;
        pa1[i] = p;
    }
}

// Combine: O = (acc0+acc1) / (lsum0+lsum1). 1 float4 per thread.
__global__ __launch_bounds__(256)
void reduce_kernel(float* __restrict__ O) {
    const int i4 = blockIdx.x * 256 + threadIdx.x;          // 0 .. 262143
    const int qi = i4 >> 2;                                 // query row (D=16 -> 4 float4/row)
    const float l = g_plsum[0][qi] + g_plsum[1][qi];
    const float inv = 1.0f / l;
    const float4 a = ((const float4*)g_pacc[0])[i4];
    const float4 c = ((const float4*)g_pacc[1])[i4];
    float4 o;
    o.x = (a.x + c.x) * inv;
    o.y = (a.y + c.y) * inv;
    o.z = (a.z + c.z) * inv;
    o.w = (a.w + c.w) * inv;
    ((float4*)O)[i4] = o;
}

extern "C" void kernel_launch(void* const* d_in, const int* in_sizes, int n_in,
                              void* d_out, int out_size) {
    const float* Q = (const float*)d_in[0];
    const float* K = (const float*)d_in[1];
    const float* V = (const float*)d_in[2];
    const int*   mask = (const int*)d_in[3];
    float* O = (float*)d_out;

    // SCALE = log(400)/log(50)/sqrt(16); fold in 2*log2(e) for the tanh exp
    const float q_prescale =
        (float)((log(400.0) / log(50.0) / 4.0) * 2.0 * 1.4426950408889634);

    dim3 grid(S_ / QTILE, B_ * H_, KSPLIT);
    attn_kernel<<<grid, QPB>>>(Q, K, V, mask, q_prescale);

    const int total4 = B_ * H_ * S_ * D_ / 4;               // 262144
    reduce_kernel<<<total4 / 256, 256>>>(O);
}